// round 10
// baseline (speedup 1.0000x reference)
#include <cuda_runtime.h>

// QuantumImagePreprocessor: Heisenberg closed form, scalar math, high occupancy.
// Each thread: 2 ow-adjacent patches (2x LDG.128 in, 2x STG.128 out).
// x: (32,224,224,1) f32, weights: (2,4,3) f32 -> out: (32,112,112,4) f32.

#define NB   32
#define IH   224
#define IW   224
#define OH   112
#define OW   112
#define NPATCH (NB * OH * OW)        // 401408
#define NPAIR  (NPATCH / 2)          // 200704
#define QW     (OW / 2)              // 56

#define THREADS 256
#define PI_F 3.14159265358979323846f

// shared coefficient layout (float4 entries):
//  sQ[w][r] = row r of S1[w] (column 1 pre-negated)
//  sC[0]=c0, sC[1]=c1, sC[2..4]=c2 (9 in xyzw,xyzw,x), sC[5..7]=c3
__global__ __launch_bounds__(THREADS)
void qip_kernel(const float* __restrict__ x,
                const float* __restrict__ weights,
                float* __restrict__ out)
{
    __shared__ float4 sQ[4][3];
    __shared__ float4 sC[8];

    int t = threadIdx.x;

    int P = blockIdx.x * THREADS + t;    // pair index
    int q = P % QW;
    const float* base = x + (8 * P - 4 * q);

    // both loads in flight before anything else
    float4 r0 = *(const float4*)(base);
    float4 r1 = *(const float4*)(base + IW);

    if (t < 4) {
        const float* ww = weights + t * 3;
        float sf, cf, st, ct, so, co;
        __sincosf(ww[0], &sf, &cf);
        __sincosf(ww[1], &st, &ct);
        __sincosf(ww[2], &so, &co);
        float M00 = ct * cf, M01 = -ct * sf, M02 = st;
        float M10 = sf,      M11 = cf;
        float M20 = -st * cf, M21 = st * sf, M22 = ct;
        sQ[t][0] = make_float4(co * M00 - so * M10, -(co * M01 - so * M11), co * M02, 0.f);
        sQ[t][1] = make_float4(so * M00 + co * M10, -(so * M01 + co * M11), so * M02, 0.f);
        sQ[t][2] = make_float4(M20, -M21, M22, 0.f);
    } else if (t == 4 || t == 5) {
        int wA = t - 4;
        const float* wa = weights + 12 + wA * 3;
        const float* wb = weights + 12 + (wA + 2) * 3;
        float sfa, cfa, sta, cta, sfb, cfb, stb, ctb;
        __sincosf(wa[0], &sfa, &cfa);
        __sincosf(wa[1], &sta, &cta);
        __sincosf(wb[0], &sfb, &cfb);
        __sincosf(wb[1], &stb, &ctb);
        float ax = -sta * cfa, ay = sta * sfa, az = cta;
        float bx = -stb * cfb, by = stb * sfb, bz = ctb;
        if (t == 4) {
            sC[0] = make_float4(bx, by, bz, 0.f);
            sC[2] = make_float4( ax * bx, -ax * by, -ax * bz, -ay * bx);
            sC[3] = make_float4( ay * by,  ay * bz, -az * bx,  az * by);
            sC[4] = make_float4( az * bz, 0.f, 0.f, 0.f);
        } else {
            sC[1] = make_float4(bx, -by, bz, 0.f);
            sC[5] = make_float4( ax * bx, -ax * by, -ax * bz,  ay * bx);
            sC[6] = make_float4( ay * by,  ay * bz, -az * bx,  az * by);
            sC[7] = make_float4( az * bz, 0.f, 0.f, 0.f);
        }
    }
    __syncthreads();

    // patch pixel sets: lane j=0 -> (r0.x,r0.y,r1.x,r1.y), j=1 -> (r0.z,r0.w,r1.z,r1.w)
    float px[2][4] = {
        { r0.x, r0.y, r1.x, r1.y },
        { r0.z, r0.w, r1.z, r1.w },
    };

    float4 res[2];
#pragma unroll
    for (int pp = 0; pp < 2; pp++) {
        float s0, cA, s1, cB, s2, cC, s3, cD;
        __sincosf(px[pp][0] * PI_F, &s0, &cA);
        __sincosf(px[pp][1] * PI_F, &s1, &cB);
        __sincosf(px[pp][2] * PI_F, &s2, &cC);
        __sincosf(px[pp][3] * PI_F, &s3, &cD);

        float n00 = s0 * cA, n02 = cA * cA;
        float n10 = s1 * cB, n12 = cB * cB;
        float n20 = s2 * cC, n22 = cC * cC;
        float n30 = s3 * cD, n32 = cD * cD;

        float4 q00 = sQ[0][0], q01 = sQ[0][1], q02 = sQ[0][2];
        float m0x = fmaf(q00.x, n00, fmaf(q00.y, s0, q00.z * n02));
        float m0y = fmaf(q01.x, n00, fmaf(q01.y, s0, q01.z * n02));
        float m0z = fmaf(q02.x, n00, fmaf(q02.y, s0, q02.z * n02));
        float4 q10 = sQ[1][0], q11 = sQ[1][1], q12 = sQ[1][2];
        float m1x = fmaf(q10.x, n10, fmaf(q10.y, s1, q10.z * n12));
        float m1y = fmaf(q11.x, n10, fmaf(q11.y, s1, q11.z * n12));
        float m1z = fmaf(q12.x, n10, fmaf(q12.y, s1, q12.z * n12));
        float4 q20 = sQ[2][0], q21 = sQ[2][1], q22 = sQ[2][2];
        float m2x = fmaf(q20.x, n20, fmaf(q20.y, s2, q20.z * n22));
        float m2y = fmaf(q21.x, n20, fmaf(q21.y, s2, q21.z * n22));
        float m2z = fmaf(q22.x, n20, fmaf(q22.y, s2, q22.z * n22));
        float4 q30 = sQ[3][0], q31 = sQ[3][1], q32 = sQ[3][2];
        float m3x = fmaf(q30.x, n30, fmaf(q30.y, s3, q30.z * n32));
        float m3y = fmaf(q31.x, n30, fmaf(q31.y, s3, q31.z * n32));
        float m3z = fmaf(q32.x, n30, fmaf(q32.y, s3, q32.z * n32));

        float xx01 = m0x * m1x;
        float yy01 = m0y * m1y;
        float zz01 = m0z * m1z;
        float xy01 = m0x * m1y;
        float yx01 = m0y * m1x;
        float yz01 = m0y * m1z;
        float zy01 = m0z * m1y;
        float axx = m2x * m3x;
        float ayx = m2y * m3x;
        float ayy = m2y * m3y;
        float axy = m2x * m3y;
        float azy = m2z * m3y;
        float azz = m2z * m3z;
        float ayz = m2y * m3z;

        float4 c0 = sC[0];
        float E0 = fmaf(c0.x, axx,
                   fmaf(c0.y, zz01 * ayx,
                        c0.z * (zz01 * m2z)));

        float4 c1 = sC[1];
        float E1 = fmaf(c1.x, xx01 * m3x,
                   fmaf(c1.y, yy01 * azy,
                        c1.z * (zz01 * azz)));

        float4 c2a = sC[2], c2b = sC[3], c2c = sC[4];
        float E2 = c2a.x * (xx01 * axx);
        E2 = fmaf(c2a.y, yy01 * ayx, E2);
        E2 = fmaf(c2a.z, yy01 * m2z, E2);
        E2 = fmaf(c2a.w, xy01 * ayy, E2);
        E2 = fmaf(c2b.x, yx01 * axy, E2);
        E2 = fmaf(c2b.y, yx01 * m3z, E2);
        E2 = fmaf(c2b.z, m1z * ayy, E2);
        E2 = fmaf(c2b.w, m0z * axy, E2);
        E2 = fmaf(c2c.x, m0z * m3z, E2);

        float4 c3a = sC[5], c3b = sC[6], c3c = sC[7];
        float E3 = c3a.x * (m0x * axx);
        E3 = fmaf(c3a.y, yz01 * ayy, E3);
        E3 = fmaf(c3a.z, zy01 * ayz, E3);
        E3 = fmaf(c3a.w, yz01 * axx, E3);
        E3 = fmaf(c3b.x, m0x * ayy, E3);
        E3 = fmaf(c3b.y, m1x * ayz, E3);
        E3 = fmaf(c3b.z, yy01 * m3x, E3);
        E3 = fmaf(c3b.w, xx01 * azy, E3);
        E3 = fmaf(c3c.x, azz, E3);

        res[pp] = make_float4(E0, E1, E2, E3);
    }

    float4* o = (float4*)out;
    o[2 * P]     = res[0];
    o[2 * P + 1] = res[1];
}

extern "C" void kernel_launch(void* const* d_in, const int* in_sizes, int n_in,
                              void* d_out, int out_size) {
    const float* x = (const float*)d_in[0];
    const float* w = (const float*)d_in[1];
    float* out = (float*)d_out;
    qip_kernel<<<NPAIR / THREADS, THREADS>>>(x, w, out);
}

// round 11
// speedup vs baseline: 1.1889x; 1.1889x over previous
#include <cuda_runtime.h>

// QuantumImagePreprocessor: Heisenberg closed form, f32x2-packed over 2 ow-adjacent
// patches. Pixel-side trig is computed BEFORE the coefficient barrier so MUFU
// latency overlaps the prologue wait. 2 LDG.128 in, 2 STG.128 out per thread.
// x: (32,224,224,1) f32, weights: (2,4,3) f32 -> out: (32,112,112,4) f32.

#define NB   32
#define IH   224
#define IW   224
#define OH   112
#define OW   112
#define NPATCH (NB * OH * OW)        // 401408
#define NPAIR  (NPATCH / 2)          // 200704
#define QW     (OW / 2)              // 56

#define THREADS 128
#define PI_F 3.14159265358979323846f

typedef unsigned long long f32x2;

__device__ __forceinline__ f32x2 pk(float lo, float hi) {
    f32x2 r; asm("mov.b64 %0, {%1, %2};" : "=l"(r) : "f"(lo), "f"(hi)); return r;
}
__device__ __forceinline__ void upk(f32x2 v, float& lo, float& hi) {
    asm("mov.b64 {%0, %1}, %2;" : "=f"(lo), "=f"(hi) : "l"(v));
}
__device__ __forceinline__ f32x2 fma2(f32x2 a, f32x2 b, f32x2 c) {
    f32x2 r; asm("fma.rn.f32x2 %0, %1, %2, %3;" : "=l"(r) : "l"(a), "l"(b), "l"(c)); return r;
}
__device__ __forceinline__ f32x2 mul2(f32x2 a, f32x2 b) {
    f32x2 r; asm("mul.rn.f32x2 %0, %1, %2;" : "=l"(r) : "l"(a), "l"(b)); return r;
}

// shared coefficient layout (float2 entries, value duplicated in both lanes):
//  [w*10 + i]  i<9 : Q[w] row-major, i=9 pad  -> ulonglong2 pairs w*5 .. w*5+4
//  [40..42] c0 ; [44..46] c1 ; [48..56] c2 ; [58..66] c3
__global__ __launch_bounds__(THREADS)
void qip_kernel(const float* __restrict__ x,
                const float* __restrict__ weights,
                float* __restrict__ out)
{
    __shared__ __align__(16) float2 sD[68];

    int t = threadIdx.x;

    int P = blockIdx.x * THREADS + t;    // pair index 0 .. NPAIR-1
    int q = P % QW;
    // input element offset of (b, 2oh, 4q): 8P - 4q
    const float* base = x + (8 * P - 4 * q);

    // loads in flight first
    float4 r0 = *(const float4*)(base);        // row 2oh
    float4 r1 = *(const float4*)(base + IW);   // row 2oh+1

    // ---- coefficient prologue (lanes 0..5 of the block) ----
    if (t < 4) {
        const float* ww = weights + t * 3;
        float sf, cf, st, ct, so, co;
        __sincosf(ww[0], &sf, &cf);
        __sincosf(ww[1], &st, &ct);
        __sincosf(ww[2], &so, &co);
        float M00 = ct * cf, M01 = -ct * sf, M02 = st;
        float M10 = sf,      M11 = cf;
        float M20 = -st * cf, M21 = st * sf, M22 = ct;
        float qq[10];
        qq[0] = co * M00 - so * M10; qq[1] = -(co * M01 - so * M11); qq[2] = co * M02;
        qq[3] = so * M00 + co * M10; qq[4] = -(so * M01 + co * M11); qq[5] = so * M02;
        qq[6] = M20;                 qq[7] = -M21;                   qq[8] = M22;
        qq[9] = 0.f;
#pragma unroll
        for (int i = 0; i < 10; i++) sD[t * 10 + i] = make_float2(qq[i], qq[i]);
    } else if (t == 4 || t == 5) {
        int wA = t - 4;
        const float* wa = weights + 12 + wA * 3;
        const float* wb = weights + 12 + (wA + 2) * 3;
        float sfa, cfa, sta, cta, sfb, cfb, stb, ctb;
        __sincosf(wa[0], &sfa, &cfa);
        __sincosf(wa[1], &sta, &cta);
        __sincosf(wb[0], &sfb, &cfb);
        __sincosf(wb[1], &stb, &ctb);
        float ax = -sta * cfa, ay = sta * sfa, az = cta;
        float bx = -stb * cfb, by = stb * sfb, bz = ctb;
        if (t == 4) {
            float c0v[4] = { bx, by, bz, 0.f };
#pragma unroll
            for (int i = 0; i < 4; i++) sD[40 + i] = make_float2(c0v[i], c0v[i]);
            float c2v[10] = { ax * bx, -ax * by, -ax * bz,
                             -ay * bx,  ay * by,  ay * bz,
                             -az * bx,  az * by,  az * bz, 0.f };
#pragma unroll
            for (int i = 0; i < 10; i++) sD[48 + i] = make_float2(c2v[i], c2v[i]);
        } else {
            float c1v[4] = { bx, -by, bz, 0.f };
#pragma unroll
            for (int i = 0; i < 4; i++) sD[44 + i] = make_float2(c1v[i], c1v[i]);
            float c3v[10] = { ax * bx, -ax * by, -ax * bz,
                              ay * bx,  ay * by,  ay * bz,
                             -az * bx,  az * by,  az * bz, 0.f };
#pragma unroll
            for (int i = 0; i < 10; i++) sD[58 + i] = make_float2(c3v[i], c3v[i]);
        }
    }

    // ---- pixel-side work BEFORE the barrier (independent of sD) ----
    // lane lo = patch j=0, lane hi = patch j=1
    float pa[4] = { r0.x, r0.y, r1.x, r1.y };
    float pb[4] = { r0.z, r0.w, r1.z, r1.w };

    f32x2 T0[4], T1[4], T2[4];
#pragma unroll
    for (int w = 0; w < 4; w++) {
        float sA, cA, sB, cB;
        __sincosf(pa[w] * PI_F, &sA, &cA);
        __sincosf(pb[w] * PI_F, &sB, &cB);
        f32x2 t1 = pk(sA, sB);        // s
        f32x2 tc = pk(cA, cB);        // c
        T1[w] = t1;
        T0[w] = mul2(t1, tc);         // s*c
        T2[w] = mul2(tc, tc);         // c*c
    }

    __syncthreads();

    const ulonglong2* Dq = (const ulonglong2*)sD;

    // ---- coefficient-side matvecs (after barrier) ----
    f32x2 m0x, m0y, m0z, m1x, m1y, m1z, m2x, m2y, m2z, m3x, m3y, m3z;
#pragma unroll
    for (int w = 0; w < 4; w++) {
        ulonglong2 j0 = Dq[w * 5 + 0];
        ulonglong2 j1 = Dq[w * 5 + 1];
        ulonglong2 j2 = Dq[w * 5 + 2];
        ulonglong2 j3 = Dq[w * 5 + 3];
        ulonglong2 j4 = Dq[w * 5 + 4];
        f32x2 rx = fma2(j0.x, T0[w], fma2(j0.y, T1[w], mul2(j1.x, T2[w])));
        f32x2 ry = fma2(j1.y, T0[w], fma2(j2.x, T1[w], mul2(j2.y, T2[w])));
        f32x2 rz = fma2(j3.x, T0[w], fma2(j3.y, T1[w], mul2(j4.x, T2[w])));
        if (w == 0) { m0x = rx; m0y = ry; m0z = rz; }
        else if (w == 1) { m1x = rx; m1y = ry; m1z = rz; }
        else if (w == 2) { m2x = rx; m2y = ry; m2z = rz; }
        else { m3x = rx; m3y = ry; m3z = rz; }
    }

    f32x2 xx01 = mul2(m0x, m1x);
    f32x2 yy01 = mul2(m0y, m1y);
    f32x2 zz01 = mul2(m0z, m1z);
    f32x2 xy01 = mul2(m0x, m1y);
    f32x2 yx01 = mul2(m0y, m1x);
    f32x2 yz01 = mul2(m0y, m1z);
    f32x2 zy01 = mul2(m0z, m1y);
    f32x2 axx = mul2(m2x, m3x);
    f32x2 ayx = mul2(m2y, m3x);
    f32x2 ayy = mul2(m2y, m3y);
    f32x2 axy = mul2(m2x, m3y);
    f32x2 azy = mul2(m2z, m3y);
    f32x2 azz = mul2(m2z, m3z);
    f32x2 ayz = mul2(m2y, m3z);

    ulonglong2 p20 = Dq[20], p21 = Dq[21];
    f32x2 E0 = fma2(p20.x, axx,
               fma2(p20.y, mul2(zz01, ayx),
                    mul2(p21.x, mul2(zz01, m2z))));

    ulonglong2 p22 = Dq[22], p23 = Dq[23];
    f32x2 E1 = fma2(p22.x, mul2(xx01, m3x),
               fma2(p22.y, mul2(yy01, azy),
                    mul2(p23.x, mul2(zz01, azz))));

    ulonglong2 p24 = Dq[24], p25 = Dq[25], p26 = Dq[26], p27 = Dq[27], p28 = Dq[28];
    f32x2 E2 =      mul2(p24.x, mul2(xx01, axx));
    E2 = fma2(p24.y, mul2(yy01, ayx), E2);
    E2 = fma2(p25.x, mul2(yy01, m2z), E2);
    E2 = fma2(p25.y, mul2(xy01, ayy), E2);
    E2 = fma2(p26.x, mul2(yx01, axy), E2);
    E2 = fma2(p26.y, mul2(yx01, m3z), E2);
    E2 = fma2(p27.x, mul2(m1z, ayy), E2);
    E2 = fma2(p27.y, mul2(m0z, axy), E2);
    E2 = fma2(p28.x, mul2(m0z, m3z), E2);

    ulonglong2 p29 = Dq[29], p30 = Dq[30], p31 = Dq[31], p32 = Dq[32], p33 = Dq[33];
    f32x2 E3 =      mul2(p29.x, mul2(m0x, axx));
    E3 = fma2(p29.y, mul2(yz01, ayy), E3);
    E3 = fma2(p30.x, mul2(zy01, ayz), E3);
    E3 = fma2(p30.y, mul2(yz01, axx), E3);
    E3 = fma2(p31.x, mul2(m0x, ayy), E3);
    E3 = fma2(p31.y, mul2(m1x, ayz), E3);
    E3 = fma2(p32.x, mul2(yy01, m3x), E3);
    E3 = fma2(p32.y, mul2(xx01, azy), E3);
    E3 = fma2(p33.x, azz, E3);

    float e0a, e0b, e1a, e1b, e2a, e2b, e3a, e3b;
    upk(E0, e0a, e0b);
    upk(E1, e1a, e1b);
    upk(E2, e2a, e2b);
    upk(E3, e3a, e3b);

    float4* o = (float4*)out;
    o[2 * P]     = make_float4(e0a, e1a, e2a, e3a);
    o[2 * P + 1] = make_float4(e0b, e1b, e2b, e3b);
}

extern "C" void kernel_launch(void* const* d_in, const int* in_sizes, int n_in,
                              void* d_out, int out_size) {
    const float* x = (const float*)d_in[0];
    const float* w = (const float*)d_in[1];
    float* out = (float*)d_out;
    qip_kernel<<<NPAIR / THREADS, THREADS>>>(x, w, out);
}

// round 12
// speedup vs baseline: 1.2442x; 1.0465x over previous
#include <cuda_runtime.h>

// QuantumImagePreprocessor: Heisenberg closed form, f32x2-packed over 2 ow-adjacent
// patches. Pixel trig BEFORE the coefficient barrier (overlaps prologue wait);
// E2/E3 accumulated as two independent half-chains (shorter critical path).
// x: (32,224,224,1) f32, weights: (2,4,3) f32 -> out: (32,112,112,4) f32.

#define NB   32
#define IH   224
#define IW   224
#define OH   112
#define OW   112
#define NPATCH (NB * OH * OW)        // 401408
#define NPAIR  (NPATCH / 2)          // 200704
#define QW     (OW / 2)              // 56

#define THREADS 128
#define PI_F 3.14159265358979323846f

typedef unsigned long long f32x2;

__device__ __forceinline__ f32x2 pk(float lo, float hi) {
    f32x2 r; asm("mov.b64 %0, {%1, %2};" : "=l"(r) : "f"(lo), "f"(hi)); return r;
}
__device__ __forceinline__ void upk(f32x2 v, float& lo, float& hi) {
    asm("mov.b64 {%0, %1}, %2;" : "=f"(lo), "=f"(hi) : "l"(v));
}
__device__ __forceinline__ f32x2 fma2(f32x2 a, f32x2 b, f32x2 c) {
    f32x2 r; asm("fma.rn.f32x2 %0, %1, %2, %3;" : "=l"(r) : "l"(a), "l"(b), "l"(c)); return r;
}
__device__ __forceinline__ f32x2 mul2(f32x2 a, f32x2 b) {
    f32x2 r; asm("mul.rn.f32x2 %0, %1, %2;" : "=l"(r) : "l"(a), "l"(b)); return r;
}
__device__ __forceinline__ f32x2 add2(f32x2 a, f32x2 b) {
    f32x2 r; asm("add.rn.f32x2 %0, %1, %2;" : "=l"(r) : "l"(a), "l"(b)); return r;
}

// shared coefficient layout (float2 entries, value duplicated in both lanes):
//  [w*10 + i]  i<9 : Q[w] row-major, i=9 pad  -> ulonglong2 pairs w*5 .. w*5+4
//  [40..42] c0 ; [44..46] c1 ; [48..56] c2 ; [58..66] c3
__global__ __launch_bounds__(THREADS)
void qip_kernel(const float* __restrict__ x,
                const float* __restrict__ weights,
                float* __restrict__ out)
{
    __shared__ __align__(16) float2 sD[68];

    int t = threadIdx.x;

    int P = blockIdx.x * THREADS + t;    // pair index 0 .. NPAIR-1
    int q = P % QW;
    const float* base = x + (8 * P - 4 * q);

    // loads in flight first
    float4 r0 = *(const float4*)(base);        // row 2oh
    float4 r1 = *(const float4*)(base + IW);   // row 2oh+1

    // ---- coefficient prologue (lanes 0..5 of warp 0) ----
    if (t < 4) {
        const float* ww = weights + t * 3;
        float sf, cf, st, ct, so, co;
        __sincosf(ww[0], &sf, &cf);
        __sincosf(ww[1], &st, &ct);
        __sincosf(ww[2], &so, &co);
        float M00 = ct * cf, M01 = -ct * sf, M02 = st;
        float M10 = sf,      M11 = cf;
        float M20 = -st * cf, M21 = st * sf, M22 = ct;
        float qq[10];
        qq[0] = co * M00 - so * M10; qq[1] = -(co * M01 - so * M11); qq[2] = co * M02;
        qq[3] = so * M00 + co * M10; qq[4] = -(so * M01 + co * M11); qq[5] = so * M02;
        qq[6] = M20;                 qq[7] = -M21;                   qq[8] = M22;
        qq[9] = 0.f;
#pragma unroll
        for (int i = 0; i < 10; i++) sD[t * 10 + i] = make_float2(qq[i], qq[i]);
    } else if (t == 4 || t == 5) {
        int wA = t - 4;
        const float* wa = weights + 12 + wA * 3;
        const float* wb = weights + 12 + (wA + 2) * 3;
        float sfa, cfa, sta, cta, sfb, cfb, stb, ctb;
        __sincosf(wa[0], &sfa, &cfa);
        __sincosf(wa[1], &sta, &cta);
        __sincosf(wb[0], &sfb, &cfb);
        __sincosf(wb[1], &stb, &ctb);
        float ax = -sta * cfa, ay = sta * sfa, az = cta;
        float bx = -stb * cfb, by = stb * sfb, bz = ctb;
        if (t == 4) {
            float c0v[4] = { bx, by, bz, 0.f };
#pragma unroll
            for (int i = 0; i < 4; i++) sD[40 + i] = make_float2(c0v[i], c0v[i]);
            float c2v[10] = { ax * bx, -ax * by, -ax * bz,
                             -ay * bx,  ay * by,  ay * bz,
                             -az * bx,  az * by,  az * bz, 0.f };
#pragma unroll
            for (int i = 0; i < 10; i++) sD[48 + i] = make_float2(c2v[i], c2v[i]);
        } else {
            float c1v[4] = { bx, -by, bz, 0.f };
#pragma unroll
            for (int i = 0; i < 4; i++) sD[44 + i] = make_float2(c1v[i], c1v[i]);
            float c3v[10] = { ax * bx, -ax * by, -ax * bz,
                              ay * bx,  ay * by,  ay * bz,
                             -az * bx,  az * by,  az * bz, 0.f };
#pragma unroll
            for (int i = 0; i < 10; i++) sD[58 + i] = make_float2(c3v[i], c3v[i]);
        }
    }

    // ---- pixel trig BEFORE the barrier (independent of sD) ----
    float pa[4] = { r0.x, r0.y, r1.x, r1.y };   // lane lo = patch j=0
    float pb[4] = { r0.z, r0.w, r1.z, r1.w };   // lane hi = patch j=1

    f32x2 T0[4], T1[4], T2[4];
#pragma unroll
    for (int w = 0; w < 4; w++) {
        float sA, cA, sB, cB;
        __sincosf(pa[w] * PI_F, &sA, &cA);
        __sincosf(pb[w] * PI_F, &sB, &cB);
        f32x2 t1 = pk(sA, sB);
        f32x2 tc = pk(cA, cB);
        T1[w] = t1;
        T0[w] = mul2(t1, tc);
        T2[w] = mul2(tc, tc);
    }

    __syncthreads();

    const ulonglong2* Dq = (const ulonglong2*)sD;

    // ---- matvecs ----
    f32x2 m0x, m0y, m0z, m1x, m1y, m1z, m2x, m2y, m2z, m3x, m3y, m3z;
#pragma unroll
    for (int w = 0; w < 4; w++) {
        ulonglong2 j0 = Dq[w * 5 + 0];
        ulonglong2 j1 = Dq[w * 5 + 1];
        ulonglong2 j2 = Dq[w * 5 + 2];
        ulonglong2 j3 = Dq[w * 5 + 3];
        ulonglong2 j4 = Dq[w * 5 + 4];
        f32x2 rx = fma2(j0.x, T0[w], fma2(j0.y, T1[w], mul2(j1.x, T2[w])));
        f32x2 ry = fma2(j1.y, T0[w], fma2(j2.x, T1[w], mul2(j2.y, T2[w])));
        f32x2 rz = fma2(j3.x, T0[w], fma2(j3.y, T1[w], mul2(j4.x, T2[w])));
        if (w == 0) { m0x = rx; m0y = ry; m0z = rz; }
        else if (w == 1) { m1x = rx; m1y = ry; m1z = rz; }
        else if (w == 2) { m2x = rx; m2y = ry; m2z = rz; }
        else { m3x = rx; m3y = ry; m3z = rz; }
    }

    f32x2 xx01 = mul2(m0x, m1x);
    f32x2 yy01 = mul2(m0y, m1y);
    f32x2 zz01 = mul2(m0z, m1z);
    f32x2 xy01 = mul2(m0x, m1y);
    f32x2 yx01 = mul2(m0y, m1x);
    f32x2 yz01 = mul2(m0y, m1z);
    f32x2 zy01 = mul2(m0z, m1y);
    f32x2 axx = mul2(m2x, m3x);
    f32x2 ayx = mul2(m2y, m3x);
    f32x2 ayy = mul2(m2y, m3y);
    f32x2 axy = mul2(m2x, m3y);
    f32x2 azy = mul2(m2z, m3y);
    f32x2 azz = mul2(m2z, m3z);
    f32x2 ayz = mul2(m2y, m3z);

    // E0/E1 first (short chains) so their unpack overlaps E2/E3 tails
    ulonglong2 p20 = Dq[20], p21 = Dq[21];
    f32x2 E0 = fma2(p20.x, axx,
               fma2(p20.y, mul2(zz01, ayx),
                    mul2(p21.x, mul2(zz01, m2z))));

    ulonglong2 p22 = Dq[22], p23 = Dq[23];
    f32x2 E1 = fma2(p22.x, mul2(xx01, m3x),
               fma2(p22.y, mul2(yy01, azy),
                    mul2(p23.x, mul2(zz01, azz))));

    float e0a, e0b, e1a, e1b;
    upk(E0, e0a, e0b);
    upk(E1, e1a, e1b);

    // E2: two independent half-chains (depth 5 -> ~half the serial latency)
    ulonglong2 p24 = Dq[24], p25 = Dq[25], p26 = Dq[26], p27 = Dq[27], p28 = Dq[28];
    f32x2 E2a =      mul2(p24.x, mul2(xx01, axx));
    E2a = fma2(p24.y, mul2(yy01, ayx), E2a);
    E2a = fma2(p25.x, mul2(yy01, m2z), E2a);
    E2a = fma2(p25.y, mul2(xy01, ayy), E2a);
    E2a = fma2(p26.x, mul2(yx01, axy), E2a);
    f32x2 E2b =      mul2(p26.y, mul2(yx01, m3z));
    E2b = fma2(p27.x, mul2(m1z, ayy), E2b);
    E2b = fma2(p27.y, mul2(m0z, axy), E2b);
    E2b = fma2(p28.x, mul2(m0z, m3z), E2b);
    f32x2 E2 = add2(E2a, E2b);

    // E3: two independent half-chains
    ulonglong2 p29 = Dq[29], p30 = Dq[30], p31 = Dq[31], p32 = Dq[32], p33 = Dq[33];
    f32x2 E3a =      mul2(p29.x, mul2(m0x, axx));
    E3a = fma2(p29.y, mul2(yz01, ayy), E3a);
    E3a = fma2(p30.x, mul2(zy01, ayz), E3a);
    E3a = fma2(p30.y, mul2(yz01, axx), E3a);
    E3a = fma2(p31.x, mul2(m0x, ayy), E3a);
    f32x2 E3b =      mul2(p31.y, mul2(m1x, ayz));
    E3b = fma2(p32.x, mul2(yy01, m3x), E3b);
    E3b = fma2(p32.y, mul2(xx01, azy), E3b);
    E3b = fma2(p33.x, azz, E3b);
    f32x2 E3 = add2(E3a, E3b);

    float e2a_, e2b_, e3a_, e3b_;
    upk(E2, e2a_, e2b_);
    upk(E3, e3a_, e3b_);

    float4* o = (float4*)out;
    o[2 * P]     = make_float4(e0a, e1a, e2a_, e3a_);
    o[2 * P + 1] = make_float4(e0b, e1b, e2b_, e3b_);
}

extern "C" void kernel_launch(void* const* d_in, const int* in_sizes, int n_in,
                              void* d_out, int out_size) {
    const float* x = (const float*)d_in[0];
    const float* w = (const float*)d_in[1];
    float* out = (float*)d_out;
    qip_kernel<<<NPAIR / THREADS, THREADS>>>(x, w, out);
}